// round 1
// baseline (speedup 1.0000x reference)
#include <cuda_runtime.h>

// Problem constants (fixed by the reference: obs [1024,64,64], w [64,2145], b [64])
#define D        64
#define HH       64
#define D_INPUT  2145
#define TILE_P   128     // paths per block
#define OBS_PAD  65      // shared row pad: bank = (65*t + d) % 32 = (t+d)%32 -> conflict-free fill

// Scratch for unpacked weights (allocation-free rule: __device__ globals)
__device__ float g_wt[HH][D * D];   // upper-triangular, zero below diagonal (1 MB)
__device__ float g_wl[HH][D];       // linear weights

// ---------------------------------------------------------------------------
// Prep: unpack packed-triangular weights into regular [i][j] layout per h.
// weights[h][0..63] = linear, weights[h][64 + base(i) + (j-i)] = W_ij (i<=j),
// base(i) = i*64 - i*(i-1)/2. Column 2144 is unused by the reference.
// ---------------------------------------------------------------------------
__global__ void prep_kernel(const float* __restrict__ w) {
    const int h = blockIdx.x;
    const float* wh = w + (size_t)h * D_INPUT;
    for (int idx = threadIdx.x; idx < D * D; idx += blockDim.x) {
        const int i = idx >> 6;
        const int j = idx & 63;
        float v = 0.0f;
        if (j >= i) {
            const int base = i * D - (i * (i - 1)) / 2;
            v = wh[D + base + (j - i)];
        }
        g_wt[h][idx] = v;
    }
    if (threadIdx.x < D) g_wl[h][threadIdx.x] = wh[threadIdx.x];
}

// ---------------------------------------------------------------------------
// Main: block = (path-tile, h). Thread = one path.
//   acc = b_h + sum_j wl_j o_j + sum_i o_i * (sum_{j>=i&~3} W_ij o_j)
// Weights via LDS.128 broadcast from shared; o-vector in 64 registers.
// ---------------------------------------------------------------------------
extern __shared__ float smem[];

__global__ __launch_bounds__(TILE_P)
void vf_kernel(const float* __restrict__ obs,
               const float* __restrict__ biases,
               float* __restrict__ out) {
    const int h   = blockIdx.y;
    const int n0  = blockIdx.x * TILE_P;
    const int tid = threadIdx.x;

    float* s_w   = smem;                       // 4096 floats
    float* s_wl  = smem + D * D;               // 64 floats
    float* s_obs = smem + D * D + D;           // TILE_P * OBS_PAD floats

    // --- Stage weights: 4096 floats = 1024 float4, 8 per thread (broadcast-friendly later)
    {
        const float4* gw4 = reinterpret_cast<const float4*>(&g_wt[h][0]);
        float4*       sw4 = reinterpret_cast<float4*>(s_w);
        #pragma unroll
        for (int k = 0; k < 8; k++) sw4[tid + TILE_P * k] = gw4[tid + TILE_P * k];
        if (tid < D / 4)
            reinterpret_cast<float4*>(s_wl)[tid] =
                reinterpret_cast<const float4*>(&g_wl[h][0])[tid];
    }

    // --- Stage obs tile coalesced: 128 paths x 16 float4 (each 256B row contiguous in GMEM)
    {
        #pragma unroll
        for (int k = 0; k < 16; k++) {
            const int f = tid + TILE_P * k;
            const int p = f >> 4;     // path within tile
            const int q = f & 15;     // float4 index within the 64-float row
            const float4 v = reinterpret_cast<const float4*>(obs)
                [(size_t)(n0 + p) * (HH * D / 4) + (size_t)h * (D / 4) + q];
            // scalar stores into padded row (pad 65 -> ~2-way store conflict, cheap)
            s_obs[p * OBS_PAD + 4 * q + 0] = v.x;
            s_obs[p * OBS_PAD + 4 * q + 1] = v.y;
            s_obs[p * OBS_PAD + 4 * q + 2] = v.z;
            s_obs[p * OBS_PAD + 4 * q + 3] = v.w;
        }
    }
    __syncthreads();

    // --- Fill o-vector (conflict-free: bank = (tid + d) % 32)
    float o[D];
    #pragma unroll
    for (int d = 0; d < D; d++) o[d] = s_obs[tid * OBS_PAD + d];

    float acc = biases[h];

    // Linear term
    #pragma unroll
    for (int j = 0; j < D; j += 4) {
        const float4 w = *reinterpret_cast<const float4*>(&s_wl[j]);
        acc += w.x * o[j] + w.y * o[j + 1] + w.z * o[j + 2] + w.w * o[j + 3];
    }

    // Triangular quadratic term: rows start at (i & ~3) for float4 alignment;
    // sub-diagonal entries inside the first vector are zero-filled by prep.
    #pragma unroll
    for (int i = 0; i < D; i++) {
        float r = 0.0f;
        #pragma unroll
        for (int j = (i & ~3); j < D; j += 4) {
            const float4 w = *reinterpret_cast<const float4*>(&s_w[i * D + j]);
            r += w.x * o[j];
            r += w.y * o[j + 1];
            r += w.z * o[j + 2];
            r += w.w * o[j + 3];
        }
        acc += o[i] * r;
    }

    out[(size_t)(n0 + tid) * HH + h] = acc;
}

// ---------------------------------------------------------------------------
extern "C" void kernel_launch(void* const* d_in, const int* in_sizes, int n_in,
                              void* d_out, int out_size) {
    const float* obs = (const float*)d_in[0];
    const float* w   = (const float*)d_in[1];
    const float* b   = (const float*)d_in[2];
    float* out       = (float*)d_out;

    const int N = in_sizes[0] / (HH * D);   // 1024

    prep_kernel<<<HH, 256>>>(w);

    const int smem_bytes = (D * D + D + TILE_P * OBS_PAD) * (int)sizeof(float); // 49,920 B
    cudaFuncSetAttribute(vf_kernel, cudaFuncAttributeMaxDynamicSharedMemorySize, smem_bytes);

    dim3 grid(N / TILE_P, HH);
    vf_kernel<<<grid, TILE_P, smem_bytes>>>(obs, b, out);
}

// round 2
// speedup vs baseline: 1.1488x; 1.1488x over previous
#include <cuda_runtime.h>

#define D        64
#define HH       64
#define D_INPUT  2145
#define PATHS_PER_BLOCK 128   // 64 threads x 2 paths
#define TPB      64
#define OBS_PAD  66           // even pad -> 8B-aligned rows for LDS.64 fills

typedef unsigned long long ull;

// __device__ scratch (allocation-free rule)
__device__ float g_wt[HH][D * D];   // upper-triangular, zero below diagonal
__device__ float g_wl[HH][D];       // linear weights

// ---------------------------------------------------------------------------
// packed f32x2 helpers (sm_103a)
// ---------------------------------------------------------------------------
__device__ __forceinline__ ull f2fma(ull a, ull b, ull c) {
    ull d;
    asm("fma.rn.f32x2 %0, %1, %2, %3;" : "=l"(d) : "l"(a), "l"(b), "l"(c));
    return d;
}
__device__ __forceinline__ ull f2add(ull a, ull b) {
    ull d;
    asm("add.rn.f32x2 %0, %1, %2;" : "=l"(d) : "l"(a), "l"(b));
    return d;
}
__device__ __forceinline__ ull dup_lo(ull p) {           // (lo, lo)
    return (p & 0xffffffffull) | (p << 32);
}
__device__ __forceinline__ ull dup_hi(ull p) {           // (hi, hi)
    return (p >> 32) | (p & 0xffffffff00000000ull);
}
__device__ __forceinline__ float hsum(ull p) {
    float lo = __uint_as_float((unsigned)(p & 0xffffffffull));
    float hi = __uint_as_float((unsigned)(p >> 32));
    return lo + hi;
}

// ---------------------------------------------------------------------------
// Prep: unpack packed-triangular weights into regular [i][j] rows, zero-filled
// below the diagonal. weights[h][64 + base(i) + (j-i)], base(i)=i*64-i*(i-1)/2.
// ---------------------------------------------------------------------------
__global__ void prep_kernel(const float* __restrict__ w) {
    const int h = blockIdx.x;
    const float* wh = w + (size_t)h * D_INPUT;
    for (int idx = threadIdx.x; idx < D * D; idx += blockDim.x) {
        const int i = idx >> 6;
        const int j = idx & 63;
        float v = 0.0f;
        if (j >= i) {
            const int base = i * D - (i * (i - 1)) / 2;
            v = wh[D + base + (j - i)];
        }
        g_wt[h][idx] = v;
    }
    if (threadIdx.x < D) g_wl[h][threadIdx.x] = wh[threadIdx.x];
}

// ---------------------------------------------------------------------------
// Main kernel: block = (128-path tile, h); 64 threads; thread owns 2 paths
// (pA = base + t, pB = base + 64 + t) and holds both o-vectors as f32x2 pairs
// in registers. Weights stream once from smem and feed BOTH paths (halved
// crossbar traffic), all math in packed f32x2.
// ---------------------------------------------------------------------------
extern __shared__ float smem[];

__device__ __forceinline__ void stage_obs(const float* __restrict__ obs,
                                          float* s_obs, int pbase, int h, int tid) {
    // 64 rows x 16 float4, 16 float4 per thread, coalesced 256B segments
    #pragma unroll
    for (int k = 0; k < 16; k++) {
        const int f = tid + TPB * k;
        const int p = f >> 4;
        const int q = f & 15;
        const float4 v = reinterpret_cast<const float4*>(obs)
            [(size_t)(pbase + p) * (HH * D / 4) + (size_t)h * (D / 4) + q];
        s_obs[p * OBS_PAD + 4 * q + 0] = v.x;
        s_obs[p * OBS_PAD + 4 * q + 1] = v.y;
        s_obs[p * OBS_PAD + 4 * q + 2] = v.z;
        s_obs[p * OBS_PAD + 4 * q + 3] = v.w;
    }
}

__global__ __launch_bounds__(TPB)
void vf_kernel(const float* __restrict__ obs,
               const float* __restrict__ biases,
               float* __restrict__ out) {
    const int h     = blockIdx.y;
    const int pbase = blockIdx.x * PATHS_PER_BLOCK;
    const int tid   = threadIdx.x;

    float* s_w   = smem;                    // 4096 floats
    float* s_wl  = smem + D * D;            // 64 floats
    float* s_obs = smem + D * D + D;        // 64 * OBS_PAD floats (reused A then B)

    // --- Stage weights (4096 floats = 1024 float4, 16/thread) + linear
    {
        const float4* gw4 = reinterpret_cast<const float4*>(&g_wt[h][0]);
        float4*       sw4 = reinterpret_cast<float4*>(s_w);
        #pragma unroll
        for (int k = 0; k < 16; k++) sw4[tid + TPB * k] = gw4[tid + TPB * k];
        if (tid < D / 4)
            reinterpret_cast<float4*>(s_wl)[tid] =
                reinterpret_cast<const float4*>(&g_wl[h][0])[tid];
    }

    // --- Stage path-half A, fill oA registers
    stage_obs(obs, s_obs, pbase, h, tid);
    __syncthreads();

    ull oA[D / 2];
    {
        const ull* prow = reinterpret_cast<const ull*>(s_obs + tid * OBS_PAD);
        #pragma unroll
        for (int m = 0; m < D / 2; m++) oA[m] = prow[m];
    }
    __syncthreads();

    // --- Stage path-half B into the same buffer, fill oB registers
    stage_obs(obs, s_obs, pbase + 64, h, tid);
    __syncthreads();

    ull oB[D / 2];
    {
        const ull* prow = reinterpret_cast<const ull*>(s_obs + tid * OBS_PAD);
        #pragma unroll
        for (int m = 0; m < D / 2; m++) oB[m] = prow[m];
    }

    // --- Linear term (packed)
    ull accA = 0ull, accB = 0ull;
    {
        const ull* wl2 = reinterpret_cast<const ull*>(s_wl);
        #pragma unroll
        for (int m = 0; m < D / 2; m++) {
            const ull w = wl2[m];
            accA = f2fma(w, oA[m], accA);
            accB = f2fma(w, oB[m], accB);
        }
    }

    // --- Triangular quadratic term. Row i starts at pair (i>>2)*2 (float4-
    // aligned); sub-diagonal entries inside the first chunk are zeros by prep.
    #pragma unroll
    for (int i = 0; i < D; i++) {
        const int j4s = i >> 2;
        const ull* wrow = reinterpret_cast<const ull*>(s_w + i * D);
        ull rA0 = 0ull, rA1 = 0ull, rB0 = 0ull, rB1 = 0ull;
        #pragma unroll
        for (int j4 = j4s; j4 < 16; j4++) {
            const ull w01 = wrow[2 * j4];
            const ull w23 = wrow[2 * j4 + 1];
            rA0 = f2fma(w01, oA[2 * j4],     rA0);
            rB0 = f2fma(w01, oB[2 * j4],     rB0);
            rA1 = f2fma(w23, oA[2 * j4 + 1], rA1);
            rB1 = f2fma(w23, oB[2 * j4 + 1], rB1);
        }
        const ull rAt = f2add(rA0, rA1);
        const ull rBt = f2add(rB0, rB1);
        const ull oiA = (i & 1) ? dup_hi(oA[i >> 1]) : dup_lo(oA[i >> 1]);
        const ull oiB = (i & 1) ? dup_hi(oB[i >> 1]) : dup_lo(oB[i >> 1]);
        accA = f2fma(oiA, rAt, accA);
        accB = f2fma(oiB, rBt, accB);
    }

    const float b = biases[h];
    out[(size_t)(pbase + tid)      * HH + h] = hsum(accA) + b;
    out[(size_t)(pbase + 64 + tid) * HH + h] = hsum(accB) + b;
}

// ---------------------------------------------------------------------------
extern "C" void kernel_launch(void* const* d_in, const int* in_sizes, int n_in,
                              void* d_out, int out_size) {
    const float* obs = (const float*)d_in[0];
    const float* w   = (const float*)d_in[1];
    const float* b   = (const float*)d_in[2];
    float* out       = (float*)d_out;

    const int N = in_sizes[0] / (HH * D);   // 1024

    prep_kernel<<<HH, 512>>>(w);

    const int smem_bytes = (D * D + D + 64 * OBS_PAD) * (int)sizeof(float); // ~33.5 KB
    cudaFuncSetAttribute(vf_kernel, cudaFuncAttributeMaxDynamicSharedMemorySize, smem_bytes);

    dim3 grid(N / PATHS_PER_BLOCK, HH);     // (8, 64) = 512 blocks
    vf_kernel<<<grid, TPB, smem_bytes>>>(obs, b, out);
}